// round 2
// baseline (speedup 1.0000x reference)
#include <cuda_runtime.h>

// Problem constants
#define BS     64
#define NSTK   64
#define NHALF  32     // NSTK/2 sampled strokes
#define COORD  32
#define SPEMB  256
#define DNIN   128
#define DNOUT  256
#define NPNT   64     // points per stroke
#define QOUT   32     // conv output width per stroke (64/2)
#define NTOTPNT (NSTK*NPNT)      // 4096
#define NBLK   (BS*NHALF)        // 2048 conv blocks
#define YTOT   (BS*DNOUT*NHALF*QOUT)  // 16777216

// Scratch (device globals; no allocation allowed)
__device__ int   g_idx[BS*NHALF];
__device__ float g_y[YTOT];
__device__ float g_ps[DNOUT*NBLK];
__device__ float g_pq[DNOUT*NBLK];
__device__ float g_mean[DNOUT];
__device__ float g_rstd[DNOUT];

// ---------------------------------------------------------------------------
// 1) Farthest point sampling. One block per batch, 64 threads (one per point).
//    Matches JAX: far0=0, dists=min(dists,d), argmax = FIRST max index.
// ---------------------------------------------------------------------------
__global__ void fps_kernel(const float* __restrict__ coor) {
    int b = blockIdx.x;
    int j = threadIdx.x;            // point index 0..63
    __shared__ float sx[NSTK][COORD + 1];   // +1 pad: avoid 64-way bank conflict
    __shared__ float sd[NSTK];
    __shared__ int   far;

    const float* base = coor + (size_t)b * NSTK * COORD;
    #pragma unroll
    for (int c = 0; c < COORD; c++) sx[j][c] = base[j * COORD + c];
    sd[j] = 1e10f;
    if (j == 0) far = 0;
    __syncthreads();

    for (int i = 0; i < NHALF; i++) {
        int f = far;
        if (j == 0) g_idx[b * NHALF + i] = f;
        float d = 0.f;
        #pragma unroll
        for (int c = 0; c < COORD; c++) {
            float t = sx[j][c] - sx[f][c];
            d += t * t;
        }
        sd[j] = fminf(sd[j], d);
        __syncthreads();
        if (j == 0) {
            float best = sd[0]; int bi = 0;
            #pragma unroll 4
            for (int k = 1; k < NSTK; k++) {
                if (sd[k] > best) { best = sd[k]; bi = k; }   // strict > keeps first max
            }
            far = bi;
        }
        __syncthreads();
    }
}

// ---------------------------------------------------------------------------
// 2) Gather sparse features: out[b][e][s] = sf[b][e][idx[b][s]]
// ---------------------------------------------------------------------------
__global__ void gather_sparse_kernel(const float* __restrict__ sf, float* __restrict__ out) {
    int t = blockIdx.x * blockDim.x + threadIdx.x;     // 64*256*32
    if (t >= BS * SPEMB * NHALF) return;
    int s = t % NHALF;
    int e = (t / NHALF) % SPEMB;
    int b = t / (NHALF * SPEMB);
    out[t] = sf[((size_t)b * SPEMB + e) * NSTK + g_idx[b * NHALF + s]];
}

// 3) Gather sampled coordinates: out[b][s][c] = coor[b][idx[b][s]][c]
__global__ void gather_coor_kernel(const float* __restrict__ coor, float* __restrict__ out) {
    int t = blockIdx.x * blockDim.x + threadIdx.x;     // 64*32*32
    if (t >= BS * NHALF * COORD) return;
    int c = t % COORD;
    int s = (t / COORD) % NHALF;
    int b = t / (COORD * NHALF);
    out[t] = coor[((size_t)b * NSTK + g_idx[b * NHALF + s]) * COORD + c];
}

// ---------------------------------------------------------------------------
// 4) Conv (1,3), stride (1,2), pad (0,1) over gathered dense features.
//    One block per (b, s). Thread t owns output channel o=t, all 32 q outputs.
//    Gathered 128x64 input tile lives in shared (all reads are broadcasts).
//    Also emits per-(o,block) partial sum / sumsq for BN (deterministic).
// ---------------------------------------------------------------------------
__global__ void __launch_bounds__(256, 2) conv_kernel(
    const float* __restrict__ dense,
    const float* __restrict__ w,
    const float* __restrict__ bias)
{
    int s = blockIdx.x;
    int b = blockIdx.y;
    int o = threadIdx.x;
    __shared__ float xs[DNIN][NPNT];   // 32 KB

    int idx = g_idx[b * NHALF + s];

    // cooperative gather: thread t loads 32 consecutive floats of row i = t/2
    {
        int i    = threadIdx.x >> 1;
        int half = threadIdx.x & 1;
        const float4* src = (const float4*)(dense + ((size_t)(b * DNIN + i)) * NTOTPNT
                                            + idx * NPNT + half * 32);
        float4* dst = (float4*)(&xs[i][half * 32]);
        #pragma unroll
        for (int m = 0; m < 8; m++) dst[m] = src[m];
    }
    __syncthreads();

    float acc[QOUT];
    #pragma unroll
    for (int q = 0; q < QOUT; q++) acc[q] = 0.f;

    const float* wrow = w + (size_t)o * DNIN * 3;

    for (int i = 0; i < DNIN; i++) {
        float w0 = wrow[i * 3 + 0];
        float w1 = wrow[i * 3 + 1];
        float w2 = wrow[i * 3 + 2];
        const float4* xr = (const float4*)(&xs[i][0]);
        float carry = 0.f;     // left zero-pad for q==0; row-to-row chunk carry otherwise
        #pragma unroll
        for (int c = 0; c < 4; c++) {
            float4 v0 = xr[c * 4 + 0], v1 = xr[c * 4 + 1];
            float4 v2 = xr[c * 4 + 2], v3 = xr[c * 4 + 3];
            float e[16];
            e[0]=v0.x; e[1]=v0.y; e[2]=v0.z; e[3]=v0.w;
            e[4]=v1.x; e[5]=v1.y; e[6]=v1.z; e[7]=v1.w;
            e[8]=v2.x; e[9]=v2.y; e[10]=v2.z; e[11]=v2.w;
            e[12]=v3.x; e[13]=v3.y; e[14]=v3.z; e[15]=v3.w;
            #pragma unroll
            for (int qq = 0; qq < 8; qq++) {
                int q  = c * 8 + qq;
                int p0 = 2 * qq;
                float prev = (p0 == 0) ? carry : e[p0 - 1];
                acc[q] += w0 * prev + w1 * e[p0] + w2 * e[p0 + 1];
            }
            carry = e[15];
        }
    }

    // bias + BN partials + store
    float bo = bias[o];
    float s1 = 0.f, s2 = 0.f;
    #pragma unroll
    for (int q = 0; q < QOUT; q++) {
        acc[q] += bo;
        s1 += acc[q];
        s2 += acc[q] * acc[q];
    }

    float4* yout = (float4*)(g_y + (((size_t)(b * DNOUT + o)) * NHALF + s) * QOUT);
    #pragma unroll
    for (int m = 0; m < 8; m++)
        yout[m] = make_float4(acc[4*m], acc[4*m+1], acc[4*m+2], acc[4*m+3]);

    int blk = b * NHALF + s;
    g_ps[o * NBLK + blk] = s1;
    g_pq[o * NBLK + blk] = s2;
}

// ---------------------------------------------------------------------------
// 5) BN stats finalize: one block per channel, deterministic tree reduce.
// ---------------------------------------------------------------------------
__global__ void bnstat_kernel() {
    int o = blockIdx.x;
    int t = threadIdx.x;
    float s1 = 0.f, s2 = 0.f;
    for (int k = t; k < NBLK; k += 256) {
        s1 += g_ps[o * NBLK + k];
        s2 += g_pq[o * NBLK + k];
    }
    __shared__ float a[256], c[256];
    a[t] = s1; c[t] = s2;
    __syncthreads();
    for (int st = 128; st > 0; st >>= 1) {
        if (t < st) { a[t] += a[t + st]; c[t] += c[t + st]; }
        __syncthreads();
    }
    if (t == 0) {
        const float N = (float)(BS * NHALF * QOUT);
        float mean = a[0] / N;
        float var  = c[0] / N - mean * mean;      // biased variance
        g_mean[o] = mean;
        g_rstd[o] = rsqrtf(var + 1e-5f);
    }
}

// ---------------------------------------------------------------------------
// 6) Normalize + affine + tanh-GELU, vectorized float4.
// ---------------------------------------------------------------------------
__device__ __forceinline__ float gelu_tanh(float x) {
    float x3 = x * x * x;
    return 0.5f * x * (1.f + tanhf(0.7978845608028654f * (x + 0.044715f * x3)));
}

__global__ void norm_kernel(const float* __restrict__ gamma,
                            const float* __restrict__ beta,
                            float* __restrict__ out)
{
    const int TOT4 = YTOT / 4;
    int t = blockIdx.x * blockDim.x + threadIdx.x;
    if (t >= TOT4) return;
    int o = (t >> 8) & (DNOUT - 1);    // 256 float4 per (b,o) row; o cycles every 256
    float r  = g_rstd[o];
    float m  = g_mean[o];
    float g  = gamma[o] * r;
    float bb = beta[o] - m * g;        // y = x*g + bb
    float4 v = ((const float4*)g_y)[t];
    float4 w;
    w.x = gelu_tanh(v.x * g + bb);
    w.y = gelu_tanh(v.y * g + bb);
    w.z = gelu_tanh(v.z * g + bb);
    w.w = gelu_tanh(v.w * g + bb);
    ((float4*)out)[t] = w;
}

// ---------------------------------------------------------------------------
// Launch: tuple output = (sparse_out[64,256,32], dense_out[64,256,1024],
//                         stk_coor_sampled[64,32,32]) concatenated.
// ---------------------------------------------------------------------------
extern "C" void kernel_launch(void* const* d_in, const int* in_sizes, int n_in,
                              void* d_out, int out_size)
{
    const float* sparse_fea = (const float*)d_in[0];  // [64,256,64]
    const float* dense_fea  = (const float*)d_in[1];  // [64,128,4096]
    const float* stk_coor   = (const float*)d_in[2];  // [64,64,32]
    const float* conv_w     = (const float*)d_in[3];  // [256,128,1,3]
    const float* conv_b     = (const float*)d_in[4];  // [256]
    const float* bn_gamma   = (const float*)d_in[5];  // [256]
    const float* bn_beta    = (const float*)d_in[6];  // [256]

    float* out_sparse = (float*)d_out;                                  // 524288
    float* out_dense  = out_sparse + BS * SPEMB * NHALF;                // 16777216
    float* out_coor   = out_dense + YTOT;                               // 65536

    fps_kernel<<<BS, NSTK>>>(stk_coor);

    gather_sparse_kernel<<<(BS * SPEMB * NHALF + 255) / 256, 256>>>(sparse_fea, out_sparse);
    gather_coor_kernel<<<(BS * NHALF * COORD + 255) / 256, 256>>>(stk_coor, out_coor);

    dim3 cgrid(NHALF, BS);
    conv_kernel<<<cgrid, 256>>>(dense_fea, conv_w, conv_b);

    bnstat_kernel<<<DNOUT, 256>>>();

    norm_kernel<<<(YTOT / 4 + 255) / 256, 256>>>(bn_gamma, bn_beta, out_dense);
}

// round 3
// speedup vs baseline: 2.6943x; 2.6943x over previous
#include <cuda_runtime.h>

// Problem constants
#define BS     64
#define NSTK   64
#define NHALF  32     // NSTK/2 sampled strokes
#define COORD  32
#define SPEMB  256
#define DNIN   128
#define DNOUT  256
#define NPNT   64     // points per stroke
#define QOUT   32     // conv output width per stroke (64/2)
#define KTOT   (DNIN*3)          // 384 GEMM K
#define NTOTPNT (NSTK*NPNT)      // 4096
#define NBLK   (BS*NHALF)        // 2048 conv blocks
#define YTOT   (BS*DNOUT*NHALF*QOUT)  // 16777216

#define KC     16                // K chunk for W staging
#define NCHUNK (KTOT/KC)         // 24
// dynamic smem: Bs[384][32] + Ws[2][KC][256]
#define SMEM_BS_FLOATS (KTOT*QOUT)        // 12288
#define SMEM_WS_FLOATS (2*KC*DNOUT)       // 8192
#define SMEM_BYTES ((SMEM_BS_FLOATS + SMEM_WS_FLOATS)*4)   // 81920

// Scratch (device globals; no allocation allowed)
__device__ int   g_idx[BS*NHALF];
__device__ float g_wt[KTOT*DNOUT];        // transposed weights [k][o]
__device__ float g_y[YTOT];
__device__ float g_ps[DNOUT*NBLK];
__device__ float g_pq[DNOUT*NBLK];
__device__ float g_mean[DNOUT];
__device__ float g_rstd[DNOUT];

// ---------------------------------------------------------------------------
// 0) Weight transpose: g_wt[k*256 + o] = w[o*384 + k]. Tiny one-shot kernel.
// ---------------------------------------------------------------------------
__global__ void wtrans_kernel(const float* __restrict__ w) {
    int e = blockIdx.x * blockDim.x + threadIdx.x;
    if (e >= DNOUT * KTOT) return;
    int o = e / KTOT;
    int k = e - o * KTOT;
    g_wt[k * DNOUT + o] = w[e];
}

// ---------------------------------------------------------------------------
// 1) Farthest point sampling. One block per batch, 64 threads (one per point).
//    Matches JAX: far0=0, dists=min(dists,d), argmax = FIRST max index.
// ---------------------------------------------------------------------------
__global__ void fps_kernel(const float* __restrict__ coor) {
    int b = blockIdx.x;
    int j = threadIdx.x;            // point index 0..63
    __shared__ float sx[NSTK][COORD + 1];
    __shared__ float sd[NSTK];
    __shared__ int   far;

    const float* base = coor + (size_t)b * NSTK * COORD;
    #pragma unroll
    for (int c = 0; c < COORD; c++) sx[j][c] = base[j * COORD + c];
    sd[j] = 1e10f;
    if (j == 0) far = 0;
    __syncthreads();

    for (int i = 0; i < NHALF; i++) {
        int f = far;
        if (j == 0) g_idx[b * NHALF + i] = f;
        float d = 0.f;
        #pragma unroll
        for (int c = 0; c < COORD; c++) {
            float t = sx[j][c] - sx[f][c];
            d += t * t;
        }
        sd[j] = fminf(sd[j], d);
        __syncthreads();
        if (j == 0) {
            float best = sd[0]; int bi = 0;
            #pragma unroll 4
            for (int k = 1; k < NSTK; k++) {
                if (sd[k] > best) { best = sd[k]; bi = k; }   // strict > keeps first max
            }
            far = bi;
        }
        __syncthreads();
    }
}

// ---------------------------------------------------------------------------
// 2) Gather sparse features: out[b][e][s] = sf[b][e][idx[b][s]]
// ---------------------------------------------------------------------------
__global__ void gather_sparse_kernel(const float* __restrict__ sf, float* __restrict__ out) {
    int t = blockIdx.x * blockDim.x + threadIdx.x;
    if (t >= BS * SPEMB * NHALF) return;
    int s = t % NHALF;
    int e = (t / NHALF) % SPEMB;
    int b = t / (NHALF * SPEMB);
    out[t] = sf[((size_t)b * SPEMB + e) * NSTK + g_idx[b * NHALF + s]];
}

// 3) Gather sampled coordinates
__global__ void gather_coor_kernel(const float* __restrict__ coor, float* __restrict__ out) {
    int t = blockIdx.x * blockDim.x + threadIdx.x;
    if (t >= BS * NHALF * COORD) return;
    int c = t % COORD;
    int s = (t / COORD) % NHALF;
    int b = t / (COORD * NHALF);
    out[t] = coor[((size_t)b * NSTK + g_idx[b * NHALF + s]) * COORD + c];
}

// ---------------------------------------------------------------------------
// 4) Conv as register-tiled SGEMM per (b,s): M=256 (o), N=32 (q), K=384.
//    Bs = im2col input in shared (built once). W streamed from L2 in KC
//    chunks via cp.async double buffering (pre-transposed -> coalesced).
//    Thread (og,qg) = (t>>3, t&7) computes an 8(o) x 4(q) register tile.
// ---------------------------------------------------------------------------
__global__ void __launch_bounds__(256, 2) conv_gemm_kernel(
    const float* __restrict__ dense,
    const float* __restrict__ bias)
{
    extern __shared__ float sm[];
    float* Bs = sm;                          // [KTOT][QOUT]
    float* Ws = sm + SMEM_BS_FLOATS;         // [2][KC][DNOUT]
    float* Xs = Ws;                          // staging overlay [128][64] (32KB)

    const int s = blockIdx.x;
    const int b = blockIdx.y;
    const int t = threadIdx.x;
    const int idx = g_idx[b * NHALF + s];

    // stage raw X tile [128][64] into Ws area
    {
        int i    = t >> 1;
        int half = t & 1;
        const float4* src = (const float4*)(dense + ((size_t)(b * DNIN + i)) * NTOTPNT
                                            + idx * NPNT + half * 32);
        float4* dst = (float4*)(Xs + i * 64 + half * 32);
        #pragma unroll
        for (int m = 0; m < 8; m++) dst[m] = src[m];
    }
    __syncthreads();

    // build im2col: Bs[k][q] = X[k/3][2q + k%3 - 1], left zero pad only
    for (int e = t; e < KTOT * QOUT; e += 256) {
        int k = e >> 5;
        int q = e & 31;
        int i = k / 3;
        int kk = k - i * 3;
        int p = 2 * q + kk - 1;
        Bs[e] = (p >= 0) ? Xs[i * 64 + p] : 0.f;
    }
    __syncthreads();   // Xs dead after this; Ws chunk loads may overwrite

    const int og = t >> 3;     // 0..31 -> o base = og*8
    const int qg = t & 7;      // 0..7  -> q base = qg*4

    float acc[8][4];
    #pragma unroll
    for (int m = 0; m < 8; m++)
        #pragma unroll
        for (int n = 0; n < 4; n++) acc[m][n] = 0.f;

    // prefetch chunk 0
    {
        const float4* src = (const float4*)(g_wt) + 0;
        float* dstb = Ws;
        #pragma unroll
        for (int j = 0; j < 4; j++) {
            int f = t + j * 256;
            unsigned dsta = (unsigned)__cvta_generic_to_shared(dstb + f * 4);
            asm volatile("cp.async.cg.shared.global [%0], [%1], 16;\n" :: "r"(dsta), "l"(src + f));
        }
        asm volatile("cp.async.commit_group;\n");
    }

    for (int c = 0; c < NCHUNK; c++) {
        if (c + 1 < NCHUNK) {
            const float4* src = (const float4*)(g_wt + (c + 1) * (KC * DNOUT));
            float* dstb = Ws + ((c + 1) & 1) * (KC * DNOUT);
            #pragma unroll
            for (int j = 0; j < 4; j++) {
                int f = t + j * 256;
                unsigned dsta = (unsigned)__cvta_generic_to_shared(dstb + f * 4);
                asm volatile("cp.async.cg.shared.global [%0], [%1], 16;\n" :: "r"(dsta), "l"(src + f));
            }
            asm volatile("cp.async.commit_group;\n");
            asm volatile("cp.async.wait_group 1;\n");
        } else {
            asm volatile("cp.async.wait_group 0;\n");
        }
        __syncthreads();

        const float* wsb = Ws + (c & 1) * (KC * DNOUT);
        const float* bsb = Bs + c * KC * QOUT;
        #pragma unroll
        for (int kk = 0; kk < KC; kk++) {
            float4 a0 = *(const float4*)(wsb + kk * DNOUT + og * 8);
            float4 a1 = *(const float4*)(wsb + kk * DNOUT + og * 8 + 4);
            float4 bv = *(const float4*)(bsb + kk * QOUT + qg * 4);
            float a[8] = {a0.x, a0.y, a0.z, a0.w, a1.x, a1.y, a1.z, a1.w};
            float bb[4] = {bv.x, bv.y, bv.z, bv.w};
            #pragma unroll
            for (int m = 0; m < 8; m++)
                #pragma unroll
                for (int n = 0; n < 4; n++)
                    acc[m][n] += a[m] * bb[n];
        }
        __syncthreads();
    }

    // epilogue: bias, store y, BN partials (deterministic shfl tree over qg)
    const int blk = b * NHALF + s;
    #pragma unroll
    for (int m = 0; m < 8; m++) {
        int o = og * 8 + m;
        float bo = bias[o];
        float4 v = make_float4(acc[m][0] + bo, acc[m][1] + bo,
                               acc[m][2] + bo, acc[m][3] + bo);
        *(float4*)(g_y + (((size_t)(b * DNOUT + o)) * NHALF + s) * QOUT + qg * 4) = v;
        float s1 = v.x + v.y + v.z + v.w;
        float s2 = v.x * v.x + v.y * v.y + v.z * v.z + v.w * v.w;
        #pragma unroll
        for (int d = 1; d < 8; d <<= 1) {
            s1 += __shfl_xor_sync(0xffffffffu, s1, d);
            s2 += __shfl_xor_sync(0xffffffffu, s2, d);
        }
        if (qg == 0) {
            g_ps[o * NBLK + blk] = s1;
            g_pq[o * NBLK + blk] = s2;
        }
    }
}

// ---------------------------------------------------------------------------
// 5) BN stats finalize: one block per channel, deterministic tree reduce.
// ---------------------------------------------------------------------------
__global__ void bnstat_kernel() {
    int o = blockIdx.x;
    int t = threadIdx.x;
    float s1 = 0.f, s2 = 0.f;
    for (int k = t; k < NBLK; k += 256) {
        s1 += g_ps[o * NBLK + k];
        s2 += g_pq[o * NBLK + k];
    }
    __shared__ float a[256], c[256];
    a[t] = s1; c[t] = s2;
    __syncthreads();
    for (int st = 128; st > 0; st >>= 1) {
        if (t < st) { a[t] += a[t + st]; c[t] += c[t + st]; }
        __syncthreads();
    }
    if (t == 0) {
        const float N = (float)(BS * NHALF * QOUT);
        float mean = a[0] / N;
        float var  = c[0] / N - mean * mean;      // biased variance
        g_mean[o] = mean;
        g_rstd[o] = rsqrtf(var + 1e-5f);
    }
}

// ---------------------------------------------------------------------------
// 6) Normalize + affine + tanh-GELU, vectorized float4.
// ---------------------------------------------------------------------------
__device__ __forceinline__ float gelu_tanh(float x) {
    float x3 = x * x * x;
    return 0.5f * x * (1.f + tanhf(0.7978845608028654f * (x + 0.044715f * x3)));
}

__global__ void norm_kernel(const float* __restrict__ gamma,
                            const float* __restrict__ beta,
                            float* __restrict__ out)
{
    const int TOT4 = YTOT / 4;
    int t = blockIdx.x * blockDim.x + threadIdx.x;
    if (t >= TOT4) return;
    int o = (t >> 8) & (DNOUT - 1);
    float r  = g_rstd[o];
    float m  = g_mean[o];
    float g  = gamma[o] * r;
    float bb = beta[o] - m * g;
    float4 v = ((const float4*)g_y)[t];
    float4 w;
    w.x = gelu_tanh(v.x * g + bb);
    w.y = gelu_tanh(v.y * g + bb);
    w.z = gelu_tanh(v.z * g + bb);
    w.w = gelu_tanh(v.w * g + bb);
    ((float4*)out)[t] = w;
}

// ---------------------------------------------------------------------------
// Launch
// ---------------------------------------------------------------------------
extern "C" void kernel_launch(void* const* d_in, const int* in_sizes, int n_in,
                              void* d_out, int out_size)
{
    const float* sparse_fea = (const float*)d_in[0];  // [64,256,64]
    const float* dense_fea  = (const float*)d_in[1];  // [64,128,4096]
    const float* stk_coor   = (const float*)d_in[2];  // [64,64,32]
    const float* conv_w     = (const float*)d_in[3];  // [256,128,1,3]
    const float* conv_b     = (const float*)d_in[4];  // [256]
    const float* bn_gamma   = (const float*)d_in[5];  // [256]
    const float* bn_beta    = (const float*)d_in[6];  // [256]

    float* out_sparse = (float*)d_out;                                  // 524288
    float* out_dense  = out_sparse + BS * SPEMB * NHALF;                // 16777216
    float* out_coor   = out_dense + YTOT;                               // 65536

    cudaFuncSetAttribute(conv_gemm_kernel,
                         cudaFuncAttributeMaxDynamicSharedMemorySize, SMEM_BYTES);

    wtrans_kernel<<<(DNOUT * KTOT + 255) / 256, 256>>>(conv_w);
    fps_kernel<<<BS, NSTK>>>(stk_coor);

    gather_sparse_kernel<<<(BS * SPEMB * NHALF + 255) / 256, 256>>>(sparse_fea, out_sparse);
    gather_coor_kernel<<<(BS * NHALF * COORD + 255) / 256, 256>>>(stk_coor, out_coor);

    dim3 cgrid(NHALF, BS);
    conv_gemm_kernel<<<cgrid, 256, SMEM_BYTES>>>(dense_fea, conv_b);

    bnstat_kernel<<<DNOUT, 256>>>();

    norm_kernel<<<(YTOT / 4 + 255) / 256, 256>>>(bn_gamma, bn_beta, out_dense);
}

// round 7
// speedup vs baseline: 3.6357x; 1.3494x over previous
#include <cuda_runtime.h>
#include <cuda_bf16.h>
#include <cstdint>

// Problem constants
#define BS     64
#define NSTK   64
#define NHALF  32
#define COORD  32
#define SPEMB  256
#define DNIN   128
#define DNOUT  256
#define NPNT   64
#define QOUT   32
#define KTOT   (DNIN*3)              // 384
#define NTOTPNT (NSTK*NPNT)          // 4096
#define YTOT   (BS*DNOUT*NHALF*QOUT) // 16777216

// GEMM: Y[256,65536] = W[256,384] x B[384,65536]; 3-term bf16 split -> K'=1152
#define NTILES 512                   // (b, sg): 128 n = 4 strokes x 32 q
#define NC     18                    // K chunks of 64 (6 per term x 3 terms)
#define KC     64
#define ABLOB_ELE (DNOUT*KC)         // 16384 bf16
#define BBLOB_ELE (128*KC)           // 8192 bf16
#define STAGES 3
#define STAGE_BYTES (ABLOB_ELE*2 + BBLOB_ELE*2)   // 49152
#define SMEM_GEMM (STAGES*STAGE_BYTES)            // 147456 (>= Ds 135168)

// Scratch (device globals; no allocation allowed)
__device__ int   g_idx[BS*NHALF];
__device__ __align__(16) __nv_bfloat16 g_Ab[12*ABLOB_ELE];                 // 384 KB
__device__ __align__(16) __nv_bfloat16 g_Bb[(size_t)NTILES*12*BBLOB_ELE]; // 100.7 MB
__device__ float g_y[YTOT];
__device__ float g_ps[DNOUT*NTILES];
__device__ float g_pq[DNOUT*NTILES];
__device__ float g_mean[DNOUT];
__device__ float g_rstd[DNOUT];

// ---------------------------------------------------------------------------
// helpers
// ---------------------------------------------------------------------------
__device__ __forceinline__ uint32_t smem_u32(const void* p) {
    uint32_t a;
    asm("{ .reg .u64 t; cvta.to.shared.u64 t, %1; cvt.u32.u64 %0, t; }" : "=r"(a) : "l"(p));
    return a;
}
__device__ __forceinline__ void cp16(uint32_t dst, const void* src) {
    asm volatile("cp.async.cg.shared.global [%0], [%1], 16;\n" :: "r"(dst), "l"(src));
}
__device__ __forceinline__ void ldsm_x4(uint32_t addr, uint32_t* r) {
    asm volatile("ldmatrix.sync.aligned.m8n8.x4.shared.b16 {%0,%1,%2,%3}, [%4];"
        : "=r"(r[0]), "=r"(r[1]), "=r"(r[2]), "=r"(r[3]) : "r"(addr));
}
__device__ __forceinline__ void mma16816(float* d, const uint32_t* a, uint32_t b0, uint32_t b1) {
    asm volatile("mma.sync.aligned.m16n8k16.row.col.f32.bf16.bf16.f32 "
        "{%0,%1,%2,%3}, {%4,%5,%6,%7}, {%8,%9}, {%0,%1,%2,%3};"
        : "+f"(d[0]), "+f"(d[1]), "+f"(d[2]), "+f"(d[3])
        : "r"(a[0]), "r"(a[1]), "r"(a[2]), "r"(a[3]), "r"(b0), "r"(b1));
}

// ---------------------------------------------------------------------------
// 1) FPS (matches JAX semantics: far0=0, min-dist, first-max argmax)
// ---------------------------------------------------------------------------
__global__ void fps_kernel(const float* __restrict__ coor) {
    int b = blockIdx.x;
    int j = threadIdx.x;
    __shared__ float sx[NSTK][COORD + 1];
    __shared__ float sd[NSTK];
    __shared__ int   far;

    const float* base = coor + (size_t)b * NSTK * COORD;
    #pragma unroll
    for (int c = 0; c < COORD; c++) sx[j][c] = base[j * COORD + c];
    sd[j] = 1e10f;
    if (j == 0) far = 0;
    __syncthreads();

    for (int i = 0; i < NHALF; i++) {
        int f = far;
        if (j == 0) g_idx[b * NHALF + i] = f;
        float d = 0.f;
        #pragma unroll
        for (int c = 0; c < COORD; c++) {
            float t = sx[j][c] - sx[f][c];
            d += t * t;
        }
        sd[j] = fminf(sd[j], d);
        __syncthreads();
        if (j == 0) {
            float best = sd[0]; int bi = 0;
            #pragma unroll 4
            for (int k = 1; k < NSTK; k++)
                if (sd[k] > best) { best = sd[k]; bi = k; }
            far = bi;
        }
        __syncthreads();
    }
}

// ---------------------------------------------------------------------------
// 2/3) gathers
// ---------------------------------------------------------------------------
__global__ void gather_sparse_kernel(const float* __restrict__ sf, float* __restrict__ out) {
    int t = blockIdx.x * blockDim.x + threadIdx.x;
    if (t >= BS * SPEMB * NHALF) return;
    int s = t % NHALF;
    int e = (t / NHALF) % SPEMB;
    int b = t / (NHALF * SPEMB);
    out[t] = sf[((size_t)b * SPEMB + e) * NSTK + g_idx[b * NHALF + s]];
}
__global__ void gather_coor_kernel(const float* __restrict__ coor, float* __restrict__ out) {
    int t = blockIdx.x * blockDim.x + threadIdx.x;
    if (t >= BS * NHALF * COORD) return;
    int c = t % COORD;
    int s = (t / COORD) % NHALF;
    int b = t / (COORD * NHALF);
    out[t] = coor[((size_t)b * NSTK + g_idx[b * NHALF + s]) * COORD + c];
}

// ---------------------------------------------------------------------------
// 4a) Weight split -> A blobs [12][256 m][64 k] bf16 (k-major, plain).
//     blob j<6: hi(W[:, j*64 .. j*64+64)); j>=6: lo.
// ---------------------------------------------------------------------------
__global__ void wsplit_kernel(const float* __restrict__ w) {
    int j = blockIdx.x;
    __nv_bfloat16* blob = g_Ab + (size_t)j * ABLOB_ELE;
    for (int e = threadIdx.x; e < ABLOB_ELE; e += 256) {
        int m  = e >> 6;
        int kc = e & 63;
        int k  = (j % 6) * 64 + kc;
        float val = w[(size_t)m * KTOT + k];
        __nv_bfloat16 hv = __float2bfloat16(val);
        blob[e] = (j < 6) ? hv : __float2bfloat16(val - __bfloat162float(hv));
    }
}

// ---------------------------------------------------------------------------
// 4b) im2col + bf16 hi/lo split -> B blobs [nt][12][128 n][64 k] (plain).
//     B[n][k] = X[b, i, idx*64 + 2q+kk-1], n = s_local*32+q, k = i*3+kk.
// ---------------------------------------------------------------------------
__global__ void __launch_bounds__(256) bsplit_kernel(const float* __restrict__ dense) {
    __shared__ float Xs[4][32][65];
    const int nt = blockIdx.x;
    const int b  = nt >> 3;
    const int sg = nt & 7;
    const int t  = threadIdx.x;

    int idx4[4];
    #pragma unroll
    for (int s = 0; s < 4; s++) idx4[s] = g_idx[b * NHALF + sg * 4 + s];

    __nv_bfloat16* bb = g_Bb + (size_t)nt * 12 * BBLOB_ELE;

    for (int ir = 0; ir < 4; ir++) {
        const int i0 = ir * 32;
        for (int e = t; e < 8192; e += 256) {
            int s_l = e >> 11;
            int rem = e & 2047;
            int i_l = rem >> 6;
            int p   = rem & 63;
            Xs[s_l][i_l][p] =
                dense[((size_t)(b * DNIN + i0 + i_l)) * NTOTPNT + idx4[s_l] * NPNT + p];
        }
        __syncthreads();
        for (int e = t; e < 12288; e += 256) {
            int n   = e / 96;
            int r   = e - n * 96;
            int i_l = r / 3;
            int kk  = r - i_l * 3;
            int s_l = n >> 5;
            int q   = n & 31;
            int p   = 2 * q + kk - 1;
            float val = (p >= 0) ? Xs[s_l][i_l][p] : 0.f;
            __nv_bfloat16 hv = __float2bfloat16(val);
            __nv_bfloat16 lv = __float2bfloat16(val - __bfloat162float(hv));
            int k  = (i0 + i_l) * 3 + kk;
            int jb = k >> 6;
            int kc = k & 63;
            bb[(size_t)jb * BBLOB_ELE + n * 64 + kc]       = hv;
            bb[(size_t)(6 + jb) * BBLOB_ELE + n * 64 + kc] = lv;
        }
        __syncthreads();
    }
}

// ---------------------------------------------------------------------------
// 5) mma.sync bf16 GEMM: CTA tile M=256 x N=128, K'=1152 (18 chunks of 64).
//    Chunk c: A blob = (c<12)? c%6 : c-6 ; B blob = (c<12)? c : c-12.
//    (terms: Ah*Bh, Ah*Bl, Al*Bh)
//    8 warps, warp tile 64x64; 3-stage cp.async pipeline; XOR-16B smem swizzle.
// ---------------------------------------------------------------------------
__global__ void __launch_bounds__(256, 1) gemm_kernel(const float* __restrict__ bias) {
    extern __shared__ char sm[];
    const uint32_t smb = smem_u32(sm);
    const int nt   = blockIdx.x;
    const int b    = nt >> 3;
    const int sg   = nt & 7;
    const int tid  = threadIdx.x;
    const int wid  = tid >> 5;
    const int lane = tid & 31;
    const int mg   = wid & 3;     // m base = mg*64
    const int ng   = wid >> 2;    // n base = ng*64

    const __nv_bfloat16* Bbase = g_Bb + (size_t)nt * 12 * BBLOB_ELE;

    // stage s: A at smb + s*STAGE_BYTES (32KB, rows 256x128B),
    //          B at +32768 (16KB, rows 128x128B). 16B-unit XOR swizzle by row&7.
    auto load_chunk = [&](int j, int s) {
        int ab  = (j < 12) ? (j % 6) : (j - 6);
        int bbv = (j < 12) ? j : (j - 12);
        const char* srcA = (const char*)(g_Ab + (size_t)ab * ABLOB_ELE);
        const char* srcB = (const char*)(Bbase + (size_t)bbv * BBLOB_ELE);
        uint32_t aB = smb + s * STAGE_BYTES;
        uint32_t bB = aB + ABLOB_ELE * 2;
        #pragma unroll
        for (int jj = 0; jj < 8; jj++) {        // A: 2048 x 16B
            int f = tid + jj * 256;
            int row = f >> 3, g = f & 7;
            cp16(aB + row * 128 + ((g * 16) ^ ((row & 7) * 16)), srcA + f * 16);
        }
        #pragma unroll
        for (int jj = 0; jj < 4; jj++) {        // B: 1024 x 16B
            int f = tid + jj * 256;
            int row = f >> 3, g = f & 7;
            cp16(bB + row * 128 + ((g * 16) ^ ((row & 7) * 16)), srcB + f * 16);
        }
        asm volatile("cp.async.commit_group;\n");
    };

    float acc[4][8][4];
    #pragma unroll
    for (int mi = 0; mi < 4; mi++)
        #pragma unroll
        for (int n8 = 0; n8 < 8; n8++)
            #pragma unroll
            for (int r = 0; r < 4; r++) acc[mi][n8][r] = 0.f;

    #pragma unroll
    for (int j = 0; j < STAGES; j++) load_chunk(j, j);

    const int rowSel = lane & 15;          // ldmatrix lane row-select
    const int kSel   = (lane >> 4) * 16;   // ldmatrix lane 16B-half select

    for (int c = 0; c < NC; c++) {
        if (c < NC - 2)      asm volatile("cp.async.wait_group 2;" ::: "memory");
        else if (c == NC - 2) asm volatile("cp.async.wait_group 1;" ::: "memory");
        else                  asm volatile("cp.async.wait_group 0;" ::: "memory");
        __syncthreads();

        const int s = c % STAGES;
        const uint32_t aB = smb + s * STAGE_BYTES;
        const uint32_t bB = aB + ABLOB_ELE * 2;

        #pragma unroll
        for (int kb = 0; kb < 4; kb++) {
            uint32_t A[4][4], Bf[4][4];
            #pragma unroll
            for (int mi = 0; mi < 4; mi++) {
                int row = mg * 64 + mi * 16 + rowSel;
                uint32_t addr = aB + row * 128 + ((kb * 32 + kSel) ^ ((row & 7) * 16));
                ldsm_x4(addr, A[mi]);
            }
            #pragma unroll
            for (int np = 0; np < 4; np++) {
                int row = ng * 64 + np * 16 + rowSel;
                uint32_t addr = bB + row * 128 + ((kb * 32 + kSel) ^ ((row & 7) * 16));
                ldsm_x4(addr, Bf[np]);
            }
            // ldmatrix reg layout per 16-n block: {0: n0-7/k0-7, 1: n8-15/k0-7,
            //  2: n0-7/k8-15, 3: n8-15/k8-15} -> (b0,b1) = (n8&1, (n8&1)+2)
            #pragma unroll
            for (int mi = 0; mi < 4; mi++)
                #pragma unroll
                for (int n8 = 0; n8 < 8; n8++)
                    mma16816(acc[mi][n8], A[mi],
                             Bf[n8 >> 1][n8 & 1], Bf[n8 >> 1][(n8 & 1) + 2]);
        }
        __syncthreads();
        if (c + STAGES < NC) load_chunk(c + STAGES, s);
    }

    // ---- epilogue: fragments -> smem Ds[256][132], then coalesced out + BN
    float* Ds = (float*)sm;
    #pragma unroll
    for (int mi = 0; mi < 4; mi++) {
        int row0 = mg * 64 + mi * 16 + (lane >> 2);
        #pragma unroll
        for (int n8 = 0; n8 < 8; n8++) {
            int col = ng * 64 + n8 * 8 + (lane & 3) * 2;
            Ds[row0 * 132 + col]       = acc[mi][n8][0];
            Ds[row0 * 132 + col + 1]   = acc[mi][n8][1];
            Ds[(row0 + 8) * 132 + col]     = acc[mi][n8][2];
            Ds[(row0 + 8) * 132 + col + 1] = acc[mi][n8][3];
        }
    }
    __syncthreads();

    // each warp handles one full 128-wide row per iteration (32 lanes x float4)
    for (int it = 0; it < 32; it++) {
        int m = it * 8 + wid;
        float bo = __ldg(bias + m);
        float4 v = *(float4*)(Ds + m * 132 + lane * 4);
        v.x += bo; v.y += bo; v.z += bo; v.w += bo;
        *(float4*)(g_y + ((size_t)(b * DNOUT + m)) * 1024 + sg * 128 + lane * 4) = v;
        float s1 = v.x + v.y + v.z + v.w;
        float s2 = v.x * v.x + v.y * v.y + v.z * v.z + v.w * v.w;
        #pragma unroll
        for (int d = 16; d > 0; d >>= 1) {
            s1 += __shfl_xor_sync(0xffffffffu, s1, d);
            s2 += __shfl_xor_sync(0xffffffffu, s2, d);
        }
        if (lane == 0) {
            g_ps[m * NTILES + nt] = s1;
            g_pq[m * NTILES + nt] = s2;
        }
    }
}

// ---------------------------------------------------------------------------
// 6) BN stats finalize
// ---------------------------------------------------------------------------
__global__ void bnstat_kernel() {
    int o = blockIdx.x;
    int t = threadIdx.x;
    float s1 = 0.f, s2 = 0.f;
    for (int k = t; k < NTILES; k += 256) {
        s1 += g_ps[o * NTILES + k];
        s2 += g_pq[o * NTILES + k];
    }
    __shared__ float a[256], c[256];
    a[t] = s1; c[t] = s2;
    __syncthreads();
    for (int st = 128; st > 0; st >>= 1) {
        if (t < st) { a[t] += a[t + st]; c[t] += c[t + st]; }
        __syncthreads();
    }
    if (t == 0) {
        const float N = (float)(BS * NHALF * QOUT);
        float mean = a[0] / N;
        float var  = c[0] / N - mean * mean;
        g_mean[o] = mean;
        g_rstd[o] = rsqrtf(var + 1e-5f);
    }
}

// ---------------------------------------------------------------------------
// 7) Normalize + affine + tanh-GELU
// ---------------------------------------------------------------------------
__device__ __forceinline__ float gelu_tanh(float x) {
    float x3 = x * x * x;
    return 0.5f * x * (1.f + tanhf(0.7978845608028654f * (x + 0.044715f * x3)));
}
__global__ void norm_kernel(const float* __restrict__ gamma,
                            const float* __restrict__ beta,
                            float* __restrict__ out)
{
    const int TOT4 = YTOT / 4;
    int t = blockIdx.x * blockDim.x + threadIdx.x;
    if (t >= TOT4) return;
    int o = (t >> 8) & (DNOUT - 1);
    float r  = g_rstd[o];
    float m  = g_mean[o];
    float g  = gamma[o] * r;
    float bb = beta[o] - m * g;
    float4 v = ((const float4*)g_y)[t];
    float4 w;
    w.x = gelu_tanh(v.x * g + bb);
    w.y = gelu_tanh(v.y * g + bb);
    w.z = gelu_tanh(v.z * g + bb);
    w.w = gelu_tanh(v.w * g + bb);
    ((float4*)out)[t] = w;
}

// ---------------------------------------------------------------------------
// Launch
// ---------------------------------------------------------------------------
extern "C" void kernel_launch(void* const* d_in, const int* in_sizes, int n_in,
                              void* d_out, int out_size)
{
    const float* sparse_fea = (const float*)d_in[0];  // [64,256,64]
    const float* dense_fea  = (const float*)d_in[1];  // [64,128,4096]
    const float* stk_coor   = (const float*)d_in[2];  // [64,64,32]
    const float* conv_w     = (const float*)d_in[3];  // [256,128,1,3]
    const float* conv_b     = (const float*)d_in[4];  // [256]
    const float* bn_gamma   = (const float*)d_in[5];  // [256]
    const float* bn_beta    = (const float*)d_in[6];  // [256]

    float* out_sparse = (float*)d_out;
    float* out_dense  = out_sparse + BS * SPEMB * NHALF;
    float* out_coor   = out_dense + YTOT;

    static bool attr_set = false;
    if (!attr_set) {
        cudaFuncSetAttribute(gemm_kernel,
                             cudaFuncAttributeMaxDynamicSharedMemorySize, SMEM_GEMM);
        attr_set = true;
    }

    fps_kernel<<<BS, NSTK>>>(stk_coor);
    wsplit_kernel<<<12, 256>>>(conv_w);
    bsplit_kernel<<<NTILES, 256>>>(dense_fea);

    gather_sparse_kernel<<<(BS * SPEMB * NHALF + 255) / 256, 256>>>(sparse_fea, out_sparse);
    gather_coor_kernel<<<(BS * NHALF * COORD + 255) / 256, 256>>>(stk_coor, out_coor);

    gemm_kernel<<<NTILES, 256, SMEM_GEMM>>>(conv_b);

    bnstat_kernel<<<DNOUT, 256>>>();
    norm_kernel<<<(YTOT / 4 + 255) / 256, 256>>>(bn_gamma, bn_beta, out_dense);
}